// round 3
// baseline (speedup 1.0000x reference)
#include <cuda_runtime.h>
#include <cstdint>

// ============================================================================
// Problem constants
// ============================================================================
constexpr int M_TOTAL = 8192;   // 4 * 2048
constexpr int N_TOTAL = 4096;   // out features
constexpr int K_TOTAL = 4096;   // in features

// GEMM tiling
constexpr int BM = 128;
constexpr int BN = 128;
constexpr int BK = 32;
constexpr int STAGES = 4;
constexpr int K_ITERS = K_TOTAL / BK;        // 128

constexpr int ROW_F = BK + 4;                // 36 floats per smem row (pad -> conflict-free)
constexpr int TILE_F = BM * ROW_F;           // 4608 floats per A or B tile
constexpr int STAGE_F = 2 * TILE_F;          // A + B per stage
constexpr int SMEM_BYTES = STAGES * STAGE_F * 4;   // 147456 bytes

constexpr int GRID_M = M_TOTAL / BM;         // 64
constexpr int GRID_N = N_TOTAL / BN;         // 32
constexpr int GROUP_M = 8;                   // L2 rasterization panel

// ============================================================================
// Device scratch (allocation-free rule: __device__ global)
// ============================================================================
__device__ float g_W[(size_t)N_TOTAL * K_TOTAL];   // 64 MB, K-major, tf32-rounded

__constant__ float c_nf4[16] = {
    -1.0f, -0.6961928009986877f, -0.5250730514526367f, -0.39491748809814453f,
    -0.28444138169288635f, -0.18477343022823334f, -0.09105003625154495f, 0.0f,
    0.07958029955625534f, 0.16093020141124725f, 0.24611230194568634f,
    0.33791524171829224f, 0.44070982933044434f, 0.5626170039176941f,
    0.7229568362236023f, 1.0f};

// ============================================================================
// PTX helpers (portable: sm_80+ features only)
// ============================================================================
__device__ __forceinline__ uint32_t smem_to_u32(const void* p) {
    uint32_t a;
    asm("{ .reg .u64 t; cvta.to.shared.u64 t, %1; cvt.u32.u64 %0, t; }"
        : "=r"(a) : "l"(p));
    return a;
}

__device__ __forceinline__ uint32_t f2tf32(float f) {
    uint32_t r;
    asm("cvt.rna.tf32.f32 %0, %1;" : "=r"(r) : "f"(f));
    return r;
}

__device__ __forceinline__ float tf32_rn_f(float f) {
    return __uint_as_float(f2tf32(f));
}

__device__ __forceinline__ void cp_async16(uint32_t smem_addr, const void* gptr) {
    asm volatile("cp.async.cg.shared.global [%0], [%1], 16;\n"
                 :: "r"(smem_addr), "l"(gptr) : "memory");
}

#define CP_ASYNC_COMMIT() asm volatile("cp.async.commit_group;\n" ::: "memory")
#define CP_ASYNC_WAIT(n)  asm volatile("cp.async.wait_group %0;\n" :: "n"(n) : "memory")

// D += A * B  (m16n8k8, tf32, fp32 accumulate)
__device__ __forceinline__ void mma_tf32(float* c, const uint32_t* a, const uint32_t* b) {
    asm volatile(
        "mma.sync.aligned.m16n8k8.row.col.f32.tf32.tf32.f32 "
        "{%0,%1,%2,%3}, {%4,%5,%6,%7}, {%8,%9}, {%0,%1,%2,%3};\n"
        : "+f"(c[0]), "+f"(c[1]), "+f"(c[2]), "+f"(c[3])
        : "r"(a[0]), "r"(a[1]), "r"(a[2]), "r"(a[3]), "r"(b[0]), "r"(b[1]));
}

// ============================================================================
// Prep kernel: NF4 dequant -> g_W (K-major, tf32-RN-rounded)
// ============================================================================
__global__ void dequant_kernel(const int* __restrict__ packed,
                               const float* __restrict__ absmax) {
    int idx = blockIdx.x * blockDim.x + threadIdx.x;  // over O * K/2 = 8388608
    int o = idx >> 11;                                 // K/2 = 2048
    int v = packed[idx];
    float am = absmax[o];
    float2 w;
    w.x = tf32_rn_f(c_nf4[(v >> 4) & 15] * am);
    w.y = tf32_rn_f(c_nf4[v & 15] * am);
    *reinterpret_cast<float2*>(&g_W[(size_t)idx * 2]) = w;
}

// ============================================================================
// GEMM: tf32 mma.sync, 128x128x32 CTA tile, 4-stage cp.async pipeline
// ============================================================================
__global__ void __launch_bounds__(256, 1) gemm_kernel(
    float* __restrict__ out, const float* __restrict__ x,
    const float* __restrict__ bias) {
    extern __shared__ float smem[];
    const uint32_t smem_u32 = smem_to_u32(smem);

    const int tid = threadIdx.x;
    const int wid = tid >> 5;
    const int lane = tid & 31;
    const int lg = lane >> 2;      // group id 0..7
    const int lt = lane & 3;       // thread-in-group 0..3

    // L2-friendly tile rasterization (panels of GROUP_M along M)
    int pid = blockIdx.x;
    int panel = pid / (GROUP_M * GRID_N);
    int first_m = panel * GROUP_M;
    int gsz = (GRID_M - first_m < GROUP_M) ? (GRID_M - first_m) : GROUP_M;
    int inpanel = pid % (GROUP_M * GRID_N);
    int m_idx = first_m + (inpanel % gsz);
    int n_idx = inpanel / gsz;

    const int m_base = m_idx * BM;
    const int n_base = n_idx * BN;

    // Warp tile: 64 (M) x 32 (N); warp grid 2 x 4
    const int warp_m = wid & 1;
    const int warp_n = wid >> 1;
    const int wm0 = warp_m * 64;
    const int wn0 = warp_n * 32;

    const float* Aglob = x + (size_t)m_base * K_TOTAL;
    const float* Bglob = g_W + (size_t)n_base * K_TOTAL;

    // per-thread load slots: 1024 16B-chunks per tile / 256 threads = 4 each
    // chunk id = tid + i*256 ; row = id/8 ; col16 = id%8
    uint32_t sA_dst[4], sB_dst[4];
    const float* gA_src[4];
    const float* gB_src[4];
    #pragma unroll
    for (int i = 0; i < 4; i++) {
        int id = tid + i * 256;
        int r = id >> 3;
        int c = id & 7;
        sA_dst[i] = smem_u32 + (uint32_t)(r * ROW_F + c * 4) * 4u;
        sB_dst[i] = sA_dst[i] + TILE_F * 4u;
        gA_src[i] = Aglob + (size_t)r * K_TOTAL + c * 4;
        gB_src[i] = Bglob + (size_t)r * K_TOTAL + c * 4;
    }

    auto load_stage = [&](int stage, int kt) {
        uint32_t soff = (uint32_t)(stage * STAGE_F) * 4u;
        int goff = kt * BK;
        #pragma unroll
        for (int i = 0; i < 4; i++) {
            cp_async16(sA_dst[i] + soff, gA_src[i] + goff);
            cp_async16(sB_dst[i] + soff, gB_src[i] + goff);
        }
    };

    // Prologue: fill STAGES-1 stages
    #pragma unroll
    for (int s = 0; s < STAGES - 1; s++) {
        load_stage(s, s);
        CP_ASYNC_COMMIT();
    }

    float c[4][4][4];
    #pragma unroll
    for (int im = 0; im < 4; im++)
        #pragma unroll
        for (int in = 0; in < 4; in++)
            #pragma unroll
            for (int q = 0; q < 4; q++) c[im][in][q] = 0.0f;

    for (int k = 0; k < K_ITERS; k++) {
        CP_ASYNC_WAIT(STAGES - 2);
        __syncthreads();

        int kn = k + STAGES - 1;
        if (kn < K_ITERS) load_stage(kn % STAGES, kn);
        CP_ASYNC_COMMIT();

        const float* As = smem + (k % STAGES) * STAGE_F;
        const float* Bs = As + TILE_F;

        #pragma unroll
        for (int s = 0; s < 4; s++) {
            uint32_t a[4][4];
            uint32_t b[4][2];
            const int kc = s * 8 + lt;
            #pragma unroll
            for (int im = 0; im < 4; im++) {
                int r0 = wm0 + im * 16 + lg;
                a[im][0] = f2tf32(As[r0 * ROW_F + kc]);
                a[im][1] = f2tf32(As[(r0 + 8) * ROW_F + kc]);
                a[im][2] = f2tf32(As[r0 * ROW_F + kc + 4]);
                a[im][3] = f2tf32(As[(r0 + 8) * ROW_F + kc + 4]);
            }
            #pragma unroll
            for (int in = 0; in < 4; in++) {
                int nn = wn0 + in * 8 + lg;
                b[in][0] = __float_as_uint(Bs[nn * ROW_F + kc]);
                b[in][1] = __float_as_uint(Bs[nn * ROW_F + kc + 4]);
            }
            #pragma unroll
            for (int im = 0; im < 4; im++)
                #pragma unroll
                for (int in = 0; in < 4; in++)
                    mma_tf32(c[im][in], a[im], b[in]);
        }
        __syncthreads();
    }

    // Epilogue: C + bias -> out (float2 stores)
    float2 bias_v[4];
    #pragma unroll
    for (int in = 0; in < 4; in++) {
        int col = n_base + wn0 + in * 8 + 2 * lt;
        bias_v[in].x = __ldg(bias + col);
        bias_v[in].y = __ldg(bias + col + 1);
    }
    #pragma unroll
    for (int im = 0; im < 4; im++) {
        int row0 = m_base + wm0 + im * 16 + lg;
        float* o0 = out + (size_t)row0 * N_TOTAL;
        float* o1 = o0 + (size_t)8 * N_TOTAL;
        #pragma unroll
        for (int in = 0; in < 4; in++) {
            int col = n_base + wn0 + in * 8 + 2 * lt;
            float2 v0, v1;
            v0.x = c[im][in][0] + bias_v[in].x;
            v0.y = c[im][in][1] + bias_v[in].y;
            v1.x = c[im][in][2] + bias_v[in].x;
            v1.y = c[im][in][3] + bias_v[in].y;
            *reinterpret_cast<float2*>(o0 + col) = v0;
            *reinterpret_cast<float2*>(o1 + col) = v1;
        }
    }
}

// ============================================================================
// Launch
// ============================================================================
extern "C" void kernel_launch(void* const* d_in, const int* in_sizes, int n_in,
                              void* d_out, int out_size) {
    const float* x = (const float*)d_in[0];
    const int* packed = (const int*)d_in[1];
    const float* absmax = (const float*)d_in[2];
    const float* bias = (const float*)d_in[3];
    float* out = (float*)d_out;

    dequant_kernel<<<(N_TOTAL * (K_TOTAL / 2)) / 256, 256>>>(packed, absmax);

    static bool attr_set = false;
    if (!attr_set) {
        cudaFuncSetAttribute(gemm_kernel,
                             cudaFuncAttributeMaxDynamicSharedMemorySize, SMEM_BYTES);
        attr_set = true;
    }
    gemm_kernel<<<GRID_M * GRID_N, 256, SMEM_BYTES>>>(out, x, bias);
}

// round 4
// speedup vs baseline: 1.3305x; 1.3305x over previous
#include <cuda_runtime.h>
#include <cstdint>

// ============================================================================
// Problem constants
// ============================================================================
constexpr int M_TOTAL = 8192;   // 4 * 2048
constexpr int N_TOTAL = 4096;   // out features
constexpr int K_TOTAL = 4096;   // in features

// GEMM tiling
constexpr int BM = 128;
constexpr int BN = 128;
constexpr int BK = 32;
constexpr int STAGES = 2;
constexpr int K_ITERS = K_TOTAL / BK;        // 128

constexpr int ROW_F = 40;                    // 32 + 8 pad: stride%32==8 ->
                                             // conflict-free LDS.64 AND STS.128
constexpr int TILE_F = BM * ROW_F;           // 5120 floats per A or B tile
constexpr int STAGE_F = 2 * TILE_F;          // A + B per stage
constexpr int SMEM_BYTES = STAGES * STAGE_F * 4;   // 81920 bytes -> 2 CTAs/SM

constexpr int GRID_M = M_TOTAL / BM;         // 64
constexpr int GRID_N = N_TOTAL / BN;         // 32
constexpr int GROUP_M = 8;                   // L2 rasterization panel

// ============================================================================
// Device scratch (allocation-free rule: __device__ globals)
// K-layout of both is PAIR-INTERLEAVED per 8-group: k0,k4,k1,k5,k2,k6,k3,k7
// so that mma fragment pairs (k, k+4) are adjacent -> LDS.64 fragment loads.
// Values are tf32-RN-rounded at prep time (no cvt in the GEMM mainloop).
// ============================================================================
__device__ float g_W[(size_t)N_TOTAL * K_TOTAL];   // 64 MB
__device__ float g_X[(size_t)M_TOTAL * K_TOTAL];   // 128 MB

__constant__ float c_nf4[16] = {
    -1.0f, -0.6961928009986877f, -0.5250730514526367f, -0.39491748809814453f,
    -0.28444138169288635f, -0.18477343022823334f, -0.09105003625154495f, 0.0f,
    0.07958029955625534f, 0.16093020141124725f, 0.24611230194568634f,
    0.33791524171829224f, 0.44070982933044434f, 0.5626170039176941f,
    0.7229568362236023f, 1.0f};

// ============================================================================
// PTX helpers (portable: sm_80+ features only; plain compute_103 target)
// ============================================================================
__device__ __forceinline__ uint32_t smem_to_u32(const void* p) {
    uint32_t a;
    asm("{ .reg .u64 t; cvta.to.shared.u64 t, %1; cvt.u32.u64 %0, t; }"
        : "=r"(a) : "l"(p));
    return a;
}

__device__ __forceinline__ float tf32_rn_f(float f) {
    uint32_t r;
    asm("cvt.rna.tf32.f32 %0, %1;" : "=r"(r) : "f"(f));
    return __uint_as_float(r);
}

__device__ __forceinline__ void cp_async16(uint32_t smem_addr, const void* gptr) {
    asm volatile("cp.async.cg.shared.global [%0], [%1], 16;\n"
                 :: "r"(smem_addr), "l"(gptr) : "memory");
}

#define CP_ASYNC_COMMIT() asm volatile("cp.async.commit_group;\n" ::: "memory")
#define CP_ASYNC_WAIT(n)  asm volatile("cp.async.wait_group %0;\n" :: "n"(n) : "memory")

// D += A * B  (m16n8k8, tf32, fp32 accumulate)
__device__ __forceinline__ void mma_tf32(float* c, const uint32_t* a, const uint32_t* b) {
    asm volatile(
        "mma.sync.aligned.m16n8k8.row.col.f32.tf32.tf32.f32 "
        "{%0,%1,%2,%3}, {%4,%5,%6,%7}, {%8,%9}, {%0,%1,%2,%3};\n"
        : "+f"(c[0]), "+f"(c[1]), "+f"(c[2]), "+f"(c[3])
        : "r"(a[0]), "r"(a[1]), "r"(a[2]), "r"(a[3]), "r"(b[0]), "r"(b[1]));
}

// ============================================================================
// Prep kernel 1: NF4 dequant -> g_W (tf32-rounded, pair-interleaved K groups)
// Each thread handles one 8-value K group = 4 packed bytes.
// ============================================================================
__global__ void dequant_kernel(const int* __restrict__ packed,
                               const float* __restrict__ absmax) {
    int g = blockIdx.x * blockDim.x + threadIdx.x;   // over O * K/8 = 2097152
    int o = g >> 9;                                   // K/8 = 512 groups per row
    float am = absmax[o];
    int4 p = *reinterpret_cast<const int4*>(packed + (size_t)g * 4);
    // p.x -> (k0,k1)  p.y -> (k2,k3)  p.z -> (k4,k5)  p.w -> (k6,k7)
    float k0 = tf32_rn_f(c_nf4[(p.x >> 4) & 15] * am);
    float k1 = tf32_rn_f(c_nf4[p.x & 15] * am);
    float k2 = tf32_rn_f(c_nf4[(p.y >> 4) & 15] * am);
    float k3 = tf32_rn_f(c_nf4[p.y & 15] * am);
    float k4 = tf32_rn_f(c_nf4[(p.z >> 4) & 15] * am);
    float k5 = tf32_rn_f(c_nf4[p.z & 15] * am);
    float k6 = tf32_rn_f(c_nf4[(p.w >> 4) & 15] * am);
    float k7 = tf32_rn_f(c_nf4[p.w & 15] * am);
    float4* dst = reinterpret_cast<float4*>(g_W + (size_t)g * 8);
    dst[0] = make_float4(k0, k4, k1, k5);   // interleave: k0,k4,k1,k5
    dst[1] = make_float4(k2, k6, k3, k7);   //             k2,k6,k3,k7
}

// ============================================================================
// Prep kernel 2: round x to tf32 -> g_X (pair-interleaved K groups)
// ============================================================================
__global__ void xprep_kernel(const float4* __restrict__ x) {
    size_t g = (size_t)blockIdx.x * blockDim.x + threadIdx.x;  // over M*K/8
    float4 lo = x[g * 2];       // k0..k3
    float4 hi = x[g * 2 + 1];   // k4..k7
    float4 o0 = make_float4(tf32_rn_f(lo.x), tf32_rn_f(hi.x),
                            tf32_rn_f(lo.y), tf32_rn_f(hi.y));
    float4 o1 = make_float4(tf32_rn_f(lo.z), tf32_rn_f(hi.z),
                            tf32_rn_f(lo.w), tf32_rn_f(hi.w));
    float4* dst = reinterpret_cast<float4*>(g_X);
    dst[g * 2] = o0;
    dst[g * 2 + 1] = o1;
}

// ============================================================================
// GEMM: tf32 mma.sync, 128x128x32 CTA tile, 2-stage cp.async, 2 CTAs/SM
// ============================================================================
__global__ void __launch_bounds__(256, 2) gemm_kernel(
    float* __restrict__ out, const float* __restrict__ bias) {
    extern __shared__ float smem[];
    const uint32_t smem_u32 = smem_to_u32(smem);

    const int tid = threadIdx.x;
    const int wid = tid >> 5;
    const int lane = tid & 31;
    const int lg = lane >> 2;      // group id 0..7
    const int lt = lane & 3;       // thread-in-group 0..3

    // L2-friendly tile rasterization (panels of GROUP_M along M)
    int pid = blockIdx.x;
    int panel = pid / (GROUP_M * GRID_N);
    int first_m = panel * GROUP_M;
    int gsz = (GRID_M - first_m < GROUP_M) ? (GRID_M - first_m) : GROUP_M;
    int inpanel = pid % (GROUP_M * GRID_N);
    int m_idx = first_m + (inpanel % gsz);
    int n_idx = inpanel / gsz;

    const int m_base = m_idx * BM;
    const int n_base = n_idx * BN;

    // Warp tile: 64 (M) x 32 (N); warp grid 2 x 4
    const int warp_m = wid & 1;
    const int warp_n = wid >> 1;
    const int wm0 = warp_m * 64;
    const int wn0 = warp_n * 32;

    const float* Aglob = g_X + (size_t)m_base * K_TOTAL;
    const float* Bglob = g_W + (size_t)n_base * K_TOTAL;

    // per-thread load slots: 1024 16B-chunks per tile / 256 threads = 4 each
    // chunk id = tid + i*256 ; row = id/8 ; chunk-in-row = id%8
    uint32_t sA_dst[4], sB_dst[4];
    const float* gA_src[4];
    const float* gB_src[4];
    #pragma unroll
    for (int i = 0; i < 4; i++) {
        int id = tid + i * 256;
        int r = id >> 3;
        int c = id & 7;
        sA_dst[i] = smem_u32 + (uint32_t)(r * ROW_F + c * 4) * 4u;
        sB_dst[i] = sA_dst[i] + TILE_F * 4u;
        gA_src[i] = Aglob + (size_t)r * K_TOTAL + c * 4;
        gB_src[i] = Bglob + (size_t)r * K_TOTAL + c * 4;
    }

    auto load_stage = [&](int stage, int kt) {
        uint32_t soff = (uint32_t)(stage * STAGE_F) * 4u;
        int goff = kt * BK;
        #pragma unroll
        for (int i = 0; i < 4; i++) {
            cp_async16(sA_dst[i] + soff, gA_src[i] + goff);
            cp_async16(sB_dst[i] + soff, gB_src[i] + goff);
        }
    };

    // Prologue: load stage 0
    load_stage(0, 0);
    CP_ASYNC_COMMIT();

    float c[4][4][4];
    #pragma unroll
    for (int im = 0; im < 4; im++)
        #pragma unroll
        for (int in = 0; in < 4; in++)
            #pragma unroll
            for (int q = 0; q < 4; q++) c[im][in][q] = 0.0f;

    for (int k = 0; k < K_ITERS; k++) {
        CP_ASYNC_WAIT(0);
        __syncthreads();

        // Prefetch next stage. Safe: every warp passed the barrier above,
        // so nobody still reads the buffer (k+1)&1 (last read at iter k-1).
        if (k + 1 < K_ITERS) load_stage((k + 1) & 1, k + 1);
        CP_ASYNC_COMMIT();

        const float* As = smem + (k & 1) * STAGE_F;
        const float* Bs = As + TILE_F;

        #pragma unroll
        for (int s = 0; s < 4; s++) {
            // interleaved layout: pair (k_lt, k_lt+4) adjacent at col s*8+2*lt
            const int col = s * 8 + 2 * lt;
            uint32_t a[4][4];
            uint32_t b[4][2];
            #pragma unroll
            for (int im = 0; im < 4; im++) {
                int r0 = wm0 + im * 16 + lg;
                float2 v0 = *reinterpret_cast<const float2*>(As + r0 * ROW_F + col);
                float2 v1 = *reinterpret_cast<const float2*>(As + (r0 + 8) * ROW_F + col);
                a[im][0] = __float_as_uint(v0.x);
                a[im][1] = __float_as_uint(v1.x);
                a[im][2] = __float_as_uint(v0.y);
                a[im][3] = __float_as_uint(v1.y);
            }
            #pragma unroll
            for (int in = 0; in < 4; in++) {
                int nn = wn0 + in * 8 + lg;
                float2 w = *reinterpret_cast<const float2*>(Bs + nn * ROW_F + col);
                b[in][0] = __float_as_uint(w.x);
                b[in][1] = __float_as_uint(w.y);
            }
            #pragma unroll
            for (int im = 0; im < 4; im++)
                #pragma unroll
                for (int in = 0; in < 4; in++)
                    mma_tf32(c[im][in], a[im], b[in]);
        }
    }

    // Epilogue: C + bias -> out (float2 stores)
    float2 bias_v[4];
    #pragma unroll
    for (int in = 0; in < 4; in++) {
        int col = n_base + wn0 + in * 8 + 2 * lt;
        bias_v[in].x = __ldg(bias + col);
        bias_v[in].y = __ldg(bias + col + 1);
    }
    #pragma unroll
    for (int im = 0; im < 4; im++) {
        int row0 = m_base + wm0 + im * 16 + lg;
        float* o0 = out + (size_t)row0 * N_TOTAL;
        float* o1 = o0 + (size_t)8 * N_TOTAL;
        #pragma unroll
        for (int in = 0; in < 4; in++) {
            int col = n_base + wn0 + in * 8 + 2 * lt;
            float2 v0, v1;
            v0.x = c[im][in][0] + bias_v[in].x;
            v0.y = c[im][in][1] + bias_v[in].y;
            v1.x = c[im][in][2] + bias_v[in].x;
            v1.y = c[im][in][3] + bias_v[in].y;
            *reinterpret_cast<float2*>(o0 + col) = v0;
            *reinterpret_cast<float2*>(o1 + col) = v1;
        }
    }
}

// ============================================================================
// Launch
// ============================================================================
extern "C" void kernel_launch(void* const* d_in, const int* in_sizes, int n_in,
                              void* d_out, int out_size) {
    const float* x = (const float*)d_in[0];
    const int* packed = (const int*)d_in[1];
    const float* absmax = (const float*)d_in[2];
    const float* bias = (const float*)d_in[3];
    float* out = (float*)d_out;

    dequant_kernel<<<(N_TOTAL * K_TOTAL / 8) / 256, 256>>>(packed, absmax);
    xprep_kernel<<<(M_TOTAL * K_TOTAL / 8) / 256, 256>>>(
        reinterpret_cast<const float4*>(x));

    static bool attr_set = false;
    if (!attr_set) {
        cudaFuncSetAttribute(gemm_kernel,
                             cudaFuncAttributeMaxDynamicSharedMemorySize, SMEM_BYTES);
        attr_set = true;
    }
    gemm_kernel<<<GRID_M * GRID_N, 256, SMEM_BYTES>>>(out, bias);
}

// round 5
// speedup vs baseline: 1.5281x; 1.1485x over previous
#include <cuda_runtime.h>
#include <cstdint>

// ============================================================================
// Problem constants
// ============================================================================
constexpr int M_TOTAL = 8192;
constexpr int N_TOTAL = 4096;
constexpr int K_TOTAL = 4096;

constexpr int BM = 128;
constexpr int BN = 128;
constexpr int BK = 32;
constexpr int STAGES = 3;
constexpr int K_ITERS = K_TOTAL / BK;        // 128

// Packed layout: 16B unit (R,G,lane) = {M[16R+lg][8G+lt], M[16R+lg][8G+lt+4],
//                                       M[16R+8+lg][8G+lt], M[16R+8+lg][8G+lt+4]}
// lane = lg*4+lt. Row-block stride = 512 groups * 512B = 256KB.
constexpr int A_STAGE_BYTES = BM * BK * 4;   // 16384
constexpr int B_STAGE_BYTES = BN * BK * 4;   // 16384
constexpr int STAGE_BYTES = A_STAGE_BYTES + B_STAGE_BYTES;  // 32768
constexpr int SMEM_BYTES = STAGES * STAGE_BYTES;            // 98304 -> 2 CTAs/SM

constexpr int GRID_M = M_TOTAL / BM;         // 64
constexpr int GRID_N = N_TOTAL / BN;         // 32
constexpr int GROUP_M = 8;

constexpr int KGROUPS = K_TOTAL / 8;         // 512 groups per row
constexpr size_t RBLK_BYTES = (size_t)KGROUPS * 512;  // 256KB per 16-row block

// ============================================================================
// Device scratch (packed tf32 layouts)
// ============================================================================
__device__ float g_W[(size_t)N_TOTAL * K_TOTAL];   // 64 MB
__device__ float g_X[(size_t)M_TOTAL * K_TOTAL];   // 128 MB

__constant__ float c_nf4[16] = {
    -1.0f, -0.6961928009986877f, -0.5250730514526367f, -0.39491748809814453f,
    -0.28444138169288635f, -0.18477343022823334f, -0.09105003625154495f, 0.0f,
    0.07958029955625534f, 0.16093020141124725f, 0.24611230194568634f,
    0.33791524171829224f, 0.44070982933044434f, 0.5626170039176941f,
    0.7229568362236023f, 1.0f};

// ============================================================================
// PTX helpers (sm_80+ portable only)
// ============================================================================
__device__ __forceinline__ uint32_t smem_to_u32(const void* p) {
    uint32_t a;
    asm("{ .reg .u64 t; cvta.to.shared.u64 t, %1; cvt.u32.u64 %0, t; }"
        : "=r"(a) : "l"(p));
    return a;
}

__device__ __forceinline__ float tf32_rn_f(float f) {
    uint32_t r;
    asm("cvt.rna.tf32.f32 %0, %1;" : "=r"(r) : "f"(f));
    return __uint_as_float(r);
}

__device__ __forceinline__ void cp_async16(uint32_t smem_addr, const void* gptr) {
    asm volatile("cp.async.cg.shared.global [%0], [%1], 16;\n"
                 :: "r"(smem_addr), "l"(gptr) : "memory");
}

#define CP_ASYNC_COMMIT() asm volatile("cp.async.commit_group;\n" ::: "memory")
#define CP_ASYNC_WAIT(n)  asm volatile("cp.async.wait_group %0;\n" :: "n"(n) : "memory")

__device__ __forceinline__ void mma_tf32(float* c, uint32_t a0, uint32_t a1,
                                         uint32_t a2, uint32_t a3,
                                         uint32_t b0, uint32_t b1) {
    asm volatile(
        "mma.sync.aligned.m16n8k8.row.col.f32.tf32.tf32.f32 "
        "{%0,%1,%2,%3}, {%4,%5,%6,%7}, {%8,%9}, {%0,%1,%2,%3};\n"
        : "+f"(c[0]), "+f"(c[1]), "+f"(c[2]), "+f"(c[3])
        : "r"(a0), "r"(a1), "r"(a2), "r"(a3), "r"(b0), "r"(b1));
}

// ============================================================================
// Prep 1: NF4 dequant -> g_W packed layout. Block = (16 rows) x (256 ks).
// shfl-based LUT (no serialized constant-bank access).
// ============================================================================
__global__ void __launch_bounds__(256) dequant_kernel(
    const int* __restrict__ packed, const float* __restrict__ absmax) {
    __shared__ float w[16 * 265];
    const int t = threadIdx.x;
    const int R = blockIdx.y;      // 16-row block of W (0..255)
    const int kc = blockIdx.x;     // 256-k chunk (0..15)

    const float lut = c_nf4[threadIdx.x & 15];

    // Read + dequant: thread -> row = t>>4, covers 16 ks (2 groups)
    {
        const int row = t >> 4;
        const int c16 = t & 15;
        const int o = R * 16 + row;
        const float am = absmax[o];
        const int* src = packed + (size_t)o * (K_TOTAL / 2) + kc * 128 + c16 * 8;
        int4 p0 = *reinterpret_cast<const int4*>(src);
        int4 p1 = *reinterpret_cast<const int4*>(src + 4);
        float* wr = w + row * 265 + c16 * 16;
        int v[8] = {p0.x, p0.y, p0.z, p0.w, p1.x, p1.y, p1.z, p1.w};
        #pragma unroll
        for (int j = 0; j < 8; j++) {
            float hi = __shfl_sync(0xffffffffu, lut, (v[j] >> 4) & 15);
            float lo = __shfl_sync(0xffffffffu, lut, v[j] & 15);
            wr[2 * j] = tf32_rn_f(hi * am);
            wr[2 * j + 1] = tf32_rn_f(lo * am);
        }
    }
    __syncthreads();

    // Write packed: thread -> (G_l = t>>3 in 0..31, lg = t&7), 4 x float4
    {
        const int Gl = t >> 3;
        const int lg = t & 7;
        float4* dst = reinterpret_cast<float4*>(
            g_W + (((size_t)R * KGROUPS + kc * 32 + Gl) * 32 + lg * 4) * 4);
        const float* w0 = w + lg * 265 + Gl * 8;
        const float* w8 = w0 + 8 * 265;
        #pragma unroll
        for (int lt = 0; lt < 4; lt++) {
            dst[lt] = make_float4(w0[lt], w0[lt + 4], w8[lt], w8[lt + 4]);
        }
    }
}

// ============================================================================
// Prep 2: x -> g_X packed layout (tf32-rounded). Block = (16 rows) x (256 ks).
// ============================================================================
__global__ void __launch_bounds__(256) xprep_kernel(const float* __restrict__ x) {
    __shared__ float w[16 * 265];
    const int t = threadIdx.x;
    const int R = blockIdx.y;      // 16-row block of X (0..511)
    const int kc = blockIdx.x;     // 256-k chunk (0..15)

    {
        const int row = t >> 4;
        const int c16 = t & 15;
        const float* src = x + (size_t)(R * 16 + row) * K_TOTAL + kc * 256 + c16 * 16;
        float* wr = w + row * 265 + c16 * 16;
        #pragma unroll
        for (int j = 0; j < 4; j++) {
            float4 v = *reinterpret_cast<const float4*>(src + 4 * j);
            wr[4 * j + 0] = tf32_rn_f(v.x);
            wr[4 * j + 1] = tf32_rn_f(v.y);
            wr[4 * j + 2] = tf32_rn_f(v.z);
            wr[4 * j + 3] = tf32_rn_f(v.w);
        }
    }
    __syncthreads();

    {
        const int Gl = t >> 3;
        const int lg = t & 7;
        float4* dst = reinterpret_cast<float4*>(
            g_X + (((size_t)R * KGROUPS + kc * 32 + Gl) * 32 + lg * 4) * 4);
        const float* w0 = w + lg * 265 + Gl * 8;
        const float* w8 = w0 + 8 * 265;
        #pragma unroll
        for (int lt = 0; lt < 4; lt++) {
            dst[lt] = make_float4(w0[lt], w0[lt + 4], w8[lt], w8[lt + 4]);
        }
    }
}

// ============================================================================
// GEMM: tf32 mma.sync, 128x128x32, 3-stage cp.async, 2 CTAs/SM,
// packed-16B fragments (all fragment loads are single LDS.128)
// ============================================================================
__global__ void __launch_bounds__(256, 2) gemm_kernel(
    float* __restrict__ out, const float* __restrict__ bias) {
    extern __shared__ char smem[];
    const uint32_t smem_u32 = smem_to_u32(smem);

    const int tid = threadIdx.x;
    const int wid = tid >> 5;
    const int lane = tid & 31;
    const int lg = lane >> 2;
    const int lt = lane & 3;

    // L2-friendly rasterization
    int pid = blockIdx.x;
    int panel = pid / (GROUP_M * GRID_N);
    int first_m = panel * GROUP_M;
    int gsz = (GRID_M - first_m < GROUP_M) ? (GRID_M - first_m) : GROUP_M;
    int inpanel = pid % (GROUP_M * GRID_N);
    int m_idx = first_m + (inpanel % gsz);
    int n_idx = inpanel / gsz;

    const int m_base = m_idx * BM;
    const int n_base = n_idx * BN;

    const int warp_m = wid & 1;     // warp tile 64x32, grid 2x4
    const int warp_n = wid >> 1;

    // ---- cp.async slot setup: 2048 16B units per stage, 8 per thread ----
    // A unit u (0..1023): Rl = u>>7, Gl = (u>>5)&3, s32 = u&31
    const char* gX = reinterpret_cast<const char*>(g_X);
    const char* gW = reinterpret_cast<const char*>(g_W);
    const char* gA_src[4];
    const char* gB_src[4];
    uint32_t sm_dst[4];
    #pragma unroll
    for (int i = 0; i < 4; i++) {
        int u = tid + i * 256;
        int Rl = u >> 7;
        int Gl = (u >> 5) & 3;
        int s32 = u & 31;
        sm_dst[i] = smem_u32 + (uint32_t)u * 16u;
        gA_src[i] = gX + (size_t)(m_base / 16 + Rl) * RBLK_BYTES + Gl * 512 + s32 * 16;
        gB_src[i] = gW + (size_t)(n_base / 16 + Rl) * RBLK_BYTES + Gl * 512 + s32 * 16;
    }

    auto load_stage = [&](int stage, int kt) {
        uint32_t soff = (uint32_t)(stage * STAGE_BYTES);
        size_t goff = (size_t)kt * 2048;   // 4 groups * 512B per k-iter
        #pragma unroll
        for (int i = 0; i < 4; i++) {
            cp_async16(sm_dst[i] + soff, gA_src[i] + goff);
            cp_async16(sm_dst[i] + soff + A_STAGE_BYTES, gB_src[i] + goff);
        }
    };

    load_stage(0, 0);
    CP_ASYNC_COMMIT();
    load_stage(1, 1);
    CP_ASYNC_COMMIT();

    float c[4][4][4];
    #pragma unroll
    for (int im = 0; im < 4; im++)
        #pragma unroll
        for (int in = 0; in < 4; in++)
            #pragma unroll
            for (int q = 0; q < 4; q++) c[im][in][q] = 0.0f;

    const uint32_t lane_off = (uint32_t)lane * 16u;

    int cur = 0;
    for (int k = 0; k < K_ITERS; k++) {
        CP_ASYNC_WAIT(1);
        __syncthreads();

        if (k + 2 < K_ITERS) {
            int nst = cur + 2;
            if (nst >= STAGES) nst -= STAGES;
            load_stage(nst, k + 2);
        }
        CP_ASYNC_COMMIT();

        const char* As = smem + cur * STAGE_BYTES;
        const char* Bs = As + A_STAGE_BYTES;

        #pragma unroll
        for (int s = 0; s < 4; s++) {
            uint4 va[4], vb[2];
            #pragma unroll
            for (int im = 0; im < 4; im++) {
                va[im] = *reinterpret_cast<const uint4*>(
                    As + ((warp_m * 4 + im) * 4 + s) * 512 + lane_off);
            }
            #pragma unroll
            for (int i2 = 0; i2 < 2; i2++) {
                vb[i2] = *reinterpret_cast<const uint4*>(
                    Bs + ((warp_n * 2 + i2) * 4 + s) * 512 + lane_off);
            }
            #pragma unroll
            for (int im = 0; im < 4; im++) {
                #pragma unroll
                for (int i2 = 0; i2 < 2; i2++) {
                    // a-regs: {[lg][k], [lg+8][k], [lg][k+4], [lg+8][k+4]}
                    mma_tf32(c[im][2 * i2], va[im].x, va[im].z, va[im].y, va[im].w,
                             vb[i2].x, vb[i2].y);
                    mma_tf32(c[im][2 * i2 + 1], va[im].x, va[im].z, va[im].y, va[im].w,
                             vb[i2].z, vb[i2].w);
                }
            }
        }
        cur++;
        if (cur == STAGES) cur = 0;
    }

    // Epilogue: C + bias -> out
    const int wn0 = warp_n * 32;
    const int wm0 = warp_m * 64;
    float2 bias_v[4];
    #pragma unroll
    for (int in = 0; in < 4; in++) {
        int col = n_base + wn0 + in * 8 + 2 * lt;
        bias_v[in].x = __ldg(bias + col);
        bias_v[in].y = __ldg(bias + col + 1);
    }
    #pragma unroll
    for (int im = 0; im < 4; im++) {
        int row0 = m_base + wm0 + im * 16 + lg;
        float* o0 = out + (size_t)row0 * N_TOTAL;
        float* o1 = o0 + (size_t)8 * N_TOTAL;
        #pragma unroll
        for (int in = 0; in < 4; in++) {
            int col = n_base + wn0 + in * 8 + 2 * lt;
            float2 v0, v1;
            v0.x = c[im][in][0] + bias_v[in].x;
            v0.y = c[im][in][1] + bias_v[in].y;
            v1.x = c[im][in][2] + bias_v[in].x;
            v1.y = c[im][in][3] + bias_v[in].y;
            *reinterpret_cast<float2*>(o0 + col) = v0;
            *reinterpret_cast<float2*>(o1 + col) = v1;
        }
    }
}

// ============================================================================
// Launch
// ============================================================================
extern "C" void kernel_launch(void* const* d_in, const int* in_sizes, int n_in,
                              void* d_out, int out_size) {
    const float* x = (const float*)d_in[0];
    const int* packed = (const int*)d_in[1];
    const float* absmax = (const float*)d_in[2];
    const float* bias = (const float*)d_in[3];
    float* out = (float*)d_out;

    dequant_kernel<<<dim3(K_TOTAL / 256, N_TOTAL / 16), 256>>>(packed, absmax);
    xprep_kernel<<<dim3(K_TOTAL / 256, M_TOTAL / 16), 256>>>(x);

    static bool attr_set = false;
    if (!attr_set) {
        cudaFuncSetAttribute(gemm_kernel,
                             cudaFuncAttributeMaxDynamicSharedMemorySize, SMEM_BYTES);
        attr_set = true;
    }
    gemm_kernel<<<GRID_M * GRID_N, 256, SMEM_BYTES>>>(out, bias);
}

// round 6
// speedup vs baseline: 2.7035x; 1.7692x over previous
#include <cuda_runtime.h>
#include <cuda_fp16.h>
#include <cstdint>

// ============================================================================
// Problem constants
// ============================================================================
constexpr int M_TOTAL = 8192;
constexpr int N_TOTAL = 4096;
constexpr int K_TOTAL = 4096;

constexpr int BM = 128;
constexpr int BN = 128;
constexpr int BK = 32;                       // 2 k16-steps per iter
constexpr int STAGES = 4;
constexpr int K_ITERS = K_TOTAL / BK;        // 128

// Packed fp16 fragment layout: 16B unit per (16-row block R, k16 group G, lane)
//   = { M[16R+lg][16G+2lt..+1], M[16R+8+lg][16G+2lt..+1],
//       M[16R+lg][16G+2lt+8..+9], M[16R+8+lg][16G+2lt+8..+9] }   (lane = lg*4+lt)
// One LDS.128 = full A fragment {a0,a1,a2,a3}; for B it = {b0,b1} of 2 n8-tiles.
constexpr int KGROUPS16 = K_TOTAL / 16;               // 256 per row-block
constexpr size_t RBLK_BYTES = (size_t)KGROUPS16 * 512; // 128 KB per 16-row block

constexpr int A_STAGE_BYTES = BM * BK * 2;   // 8192
constexpr int B_STAGE_BYTES = BN * BK * 2;   // 8192
constexpr int STAGE_BYTES = A_STAGE_BYTES + B_STAGE_BYTES;  // 16384
constexpr int SMEM_BYTES = STAGES * STAGE_BYTES;            // 65536 -> 2 CTAs/SM

constexpr int GRID_M = M_TOTAL / BM;         // 64
constexpr int GRID_N = N_TOTAL / BN;         // 32
constexpr int GROUP_M = 8;

// ============================================================================
// Device scratch (packed fp16 layouts)
// ============================================================================
__device__ __half g_W[(size_t)N_TOTAL * K_TOTAL];   // 32 MB
__device__ __half g_X[(size_t)M_TOTAL * K_TOTAL];   // 64 MB

__constant__ float c_nf4[16] = {
    -1.0f, -0.6961928009986877f, -0.5250730514526367f, -0.39491748809814453f,
    -0.28444138169288635f, -0.18477343022823334f, -0.09105003625154495f, 0.0f,
    0.07958029955625534f, 0.16093020141124725f, 0.24611230194568634f,
    0.33791524171829224f, 0.44070982933044434f, 0.5626170039176941f,
    0.7229568362236023f, 1.0f};

// ============================================================================
// PTX helpers (sm_80+ portable)
// ============================================================================
__device__ __forceinline__ uint32_t smem_to_u32(const void* p) {
    uint32_t a;
    asm("{ .reg .u64 t; cvta.to.shared.u64 t, %1; cvt.u32.u64 %0, t; }"
        : "=r"(a) : "l"(p));
    return a;
}

__device__ __forceinline__ void cp_async16(uint32_t smem_addr, const void* gptr) {
    asm volatile("cp.async.cg.shared.global [%0], [%1], 16;\n"
                 :: "r"(smem_addr), "l"(gptr) : "memory");
}

#define CP_ASYNC_COMMIT() asm volatile("cp.async.commit_group;\n" ::: "memory")
#define CP_ASYNC_WAIT(n)  asm volatile("cp.async.wait_group %0;\n" :: "n"(n) : "memory")

// D += A * B : m16n8k16 fp16 inputs, fp32 accumulate
__device__ __forceinline__ void mma_f16(float* c, uint32_t a0, uint32_t a1,
                                        uint32_t a2, uint32_t a3,
                                        uint32_t b0, uint32_t b1) {
    asm volatile(
        "mma.sync.aligned.m16n8k16.row.col.f32.f16.f16.f32 "
        "{%0,%1,%2,%3}, {%4,%5,%6,%7}, {%8,%9}, {%0,%1,%2,%3};\n"
        : "+f"(c[0]), "+f"(c[1]), "+f"(c[2]), "+f"(c[3])
        : "r"(a0), "r"(a1), "r"(a2), "r"(a3), "r"(b0), "r"(b1));
}

// ============================================================================
// Shared pack helper: smem tile (16 rows x 256 ks, pitch 264 halves) -> packed
// global units. Conflict-free reads (verified bank math).
// ============================================================================
constexpr int WPITCH = 264;   // halves; 528 bytes; /4 = 132 = 4 mod 32

__device__ __forceinline__ void pack_tile(const __half* wsm, __half* gdst,
                                          size_t blk_unit_base, int t) {
    const int lane = t & 31;
    const int lg = lane >> 2;
    const int lt = lane & 3;
    #pragma unroll
    for (int p = 0; p < 2; p++) {
        const int G = (t >> 5) + p * 8;          // k16 group in chunk (0..15)
        const int col = 16 * G + 2 * lt;
        uint4 u;
        u.x = *reinterpret_cast<const uint32_t*>(wsm + lg * WPITCH + col);
        u.y = *reinterpret_cast<const uint32_t*>(wsm + (lg + 8) * WPITCH + col);
        u.z = *reinterpret_cast<const uint32_t*>(wsm + lg * WPITCH + col + 8);
        u.w = *reinterpret_cast<const uint32_t*>(wsm + (lg + 8) * WPITCH + col + 8);
        reinterpret_cast<uint4*>(gdst)[blk_unit_base + (size_t)G * 32 + lane] = u;
    }
}

// ============================================================================
// Prep 1: NF4 dequant -> g_W packed fp16. Block = 16 rows x 256 ks.
// ============================================================================
__global__ void __launch_bounds__(256) dequant_kernel(
    const int* __restrict__ packed, const float* __restrict__ absmax) {
    __shared__ __half w[16 * WPITCH];
    const int t = threadIdx.x;
    const int R = blockIdx.y;      // 16-row block of W
    const int kc = blockIdx.x;     // 256-k chunk

    const float lut = c_nf4[t & 15];

    {
        const int row = t >> 4;
        const int c16 = t & 15;
        const int o = R * 16 + row;
        const float am = absmax[o];
        const int* src = packed + (size_t)o * (K_TOTAL / 2) + kc * 128 + c16 * 8;
        int4 p0 = *reinterpret_cast<const int4*>(src);
        int4 p1 = *reinterpret_cast<const int4*>(src + 4);
        __half* wr = w + row * WPITCH + c16 * 16;
        int v[8] = {p0.x, p0.y, p0.z, p0.w, p1.x, p1.y, p1.z, p1.w};
        #pragma unroll
        for (int j = 0; j < 8; j++) {
            float hi = __shfl_sync(0xffffffffu, lut, (v[j] >> 4) & 15);
            float lo = __shfl_sync(0xffffffffu, lut, v[j] & 15);
            wr[2 * j] = __float2half_rn(hi * am);
            wr[2 * j + 1] = __float2half_rn(lo * am);
        }
    }
    __syncthreads();

    pack_tile(w, g_W, ((size_t)R * KGROUPS16 + kc * 16) * 32, t);
}

// ============================================================================
// Prep 2: x (fp32) -> g_X packed fp16. Block = 16 rows x 256 ks.
// ============================================================================
__global__ void __launch_bounds__(256) xprep_kernel(const float* __restrict__ x) {
    __shared__ __half w[16 * WPITCH];
    const int t = threadIdx.x;
    const int R = blockIdx.y;
    const int kc = blockIdx.x;

    {
        const int row = t >> 4;
        const int c16 = t & 15;
        const float* src = x + (size_t)(R * 16 + row) * K_TOTAL + kc * 256 + c16 * 16;
        __half* wr = w + row * WPITCH + c16 * 16;
        #pragma unroll
        for (int j = 0; j < 4; j++) {
            float4 v = *reinterpret_cast<const float4*>(src + 4 * j);
            wr[4 * j + 0] = __float2half_rn(v.x);
            wr[4 * j + 1] = __float2half_rn(v.y);
            wr[4 * j + 2] = __float2half_rn(v.z);
            wr[4 * j + 3] = __float2half_rn(v.w);
        }
    }
    __syncthreads();

    pack_tile(w, g_X, ((size_t)R * KGROUPS16 + kc * 16) * 32, t);
}

// ============================================================================
// GEMM: fp16 mma.sync m16n8k16, 128x128x32, 4-stage cp.async, 2 CTAs/SM
// ============================================================================
__global__ void __launch_bounds__(256, 2) gemm_kernel(
    float* __restrict__ out, const float* __restrict__ bias) {
    extern __shared__ char smem[];
    const uint32_t smem_u32 = smem_to_u32(smem);

    const int tid = threadIdx.x;
    const int wid = tid >> 5;
    const int lane = tid & 31;
    const int lg = lane >> 2;
    const int lt = lane & 3;

    // L2-friendly rasterization
    int pid = blockIdx.x;
    int panel = pid / (GROUP_M * GRID_N);
    int first_m = panel * GROUP_M;
    int gsz = (GRID_M - first_m < GROUP_M) ? (GRID_M - first_m) : GROUP_M;
    int inpanel = pid % (GROUP_M * GRID_N);
    int m_idx = first_m + (inpanel % gsz);
    int n_idx = inpanel / gsz;

    const int m_base = m_idx * BM;
    const int n_base = n_idx * BN;

    const int warp_m = wid & 1;     // warp tile 64x32: grid 2(M) x 4(N)
    const int warp_n = wid >> 1;

    // cp.async slots: per stage A = 512 units of 16B, B = 512 units.
    // unit u: Rl = u>>6 (row-block 0..7), g = (u>>5)&1, s32 = u&31
    const char* gX = reinterpret_cast<const char*>(g_X);
    const char* gW = reinterpret_cast<const char*>(g_W);
    const char* gA_src[2];
    const char* gB_src[2];
    uint32_t smA_dst[2], smB_dst[2];
    #pragma unroll
    for (int i = 0; i < 2; i++) {
        int u = tid + i * 256;
        int Rl = u >> 6;
        int g = (u >> 5) & 1;
        int s32 = u & 31;
        smA_dst[i] = smem_u32 + (uint32_t)u * 16u;
        smB_dst[i] = smA_dst[i] + A_STAGE_BYTES;
        gA_src[i] = gX + (size_t)(m_base / 16 + Rl) * RBLK_BYTES + g * 512 + s32 * 16;
        gB_src[i] = gW + (size_t)(n_base / 16 + Rl) * RBLK_BYTES + g * 512 + s32 * 16;
    }

    auto load_stage = [&](int stage, int kt) {
        uint32_t soff = (uint32_t)(stage * STAGE_BYTES);
        size_t goff = (size_t)kt * 1024;   // 2 k16-groups * 512B per k-iter
        #pragma unroll
        for (int i = 0; i < 2; i++) {
            cp_async16(smA_dst[i] + soff, gA_src[i] + goff);
            cp_async16(smB_dst[i] + soff, gB_src[i] + goff);
        }
    };

    #pragma unroll
    for (int s = 0; s < STAGES - 1; s++) {
        load_stage(s, s);
        CP_ASYNC_COMMIT();
    }

    float c[4][4][4];
    #pragma unroll
    for (int im = 0; im < 4; im++)
        #pragma unroll
        for (int in = 0; in < 4; in++)
            #pragma unroll
            for (int q = 0; q < 4; q++) c[im][in][q] = 0.0f;

    const uint32_t lane_off = (uint32_t)lane * 16u;

    int cur = 0;
    for (int k = 0; k < K_ITERS; k++) {
        CP_ASYNC_WAIT(STAGES - 2);
        __syncthreads();

        if (k + STAGES - 1 < K_ITERS) {
            int nst = cur + STAGES - 1;
            if (nst >= STAGES) nst -= STAGES;
            load_stage(nst, k + STAGES - 1);
        }
        CP_ASYNC_COMMIT();

        const char* As = smem + cur * STAGE_BYTES;
        const char* Bs = As + A_STAGE_BYTES;

        #pragma unroll
        for (int g = 0; g < 2; g++) {
            uint4 va[4], vb[2];
            #pragma unroll
            for (int im = 0; im < 4; im++) {
                va[im] = *reinterpret_cast<const uint4*>(
                    As + (((warp_m * 4 + im) * 2 + g) * 512) + lane_off);
            }
            #pragma unroll
            for (int j = 0; j < 2; j++) {
                vb[j] = *reinterpret_cast<const uint4*>(
                    Bs + (((warp_n * 2 + j) * 2 + g) * 512) + lane_off);
            }
            #pragma unroll
            for (int im = 0; im < 4; im++) {
                #pragma unroll
                for (int j = 0; j < 2; j++) {
                    // unit regs: x={lg,b0}, y={lg+8,b0}, z={lg,b1}, w={lg+8,b1}
                    mma_f16(c[im][2 * j], va[im].x, va[im].y, va[im].z, va[im].w,
                            vb[j].x, vb[j].z);
                    mma_f16(c[im][2 * j + 1], va[im].x, va[im].y, va[im].z, va[im].w,
                            vb[j].y, vb[j].w);
                }
            }
        }
        cur++;
        if (cur == STAGES) cur = 0;
    }

    // Epilogue: C + bias -> out
    const int wn0 = warp_n * 32;
    const int wm0 = warp_m * 64;
    float2 bias_v[4];
    #pragma unroll
    for (int in = 0; in < 4; in++) {
        int col = n_base + wn0 + in * 8 + 2 * lt;
        bias_v[in].x = __ldg(bias + col);
        bias_v[in].y = __ldg(bias + col + 1);
    }
    #pragma unroll
    for (int im = 0; im < 4; im++) {
        int row0 = m_base + wm0 + im * 16 + lg;
        float* o0 = out + (size_t)row0 * N_TOTAL;
        float* o1 = o0 + (size_t)8 * N_TOTAL;
        #pragma unroll
        for (int in = 0; in < 4; in++) {
            int col = n_base + wn0 + in * 8 + 2 * lt;
            float2 v0, v1;
            v0.x = c[im][in][0] + bias_v[in].x;
            v0.y = c[im][in][1] + bias_v[in].y;
            v1.x = c[im][in][2] + bias_v[in].x;
            v1.y = c[im][in][3] + bias_v[in].y;
            *reinterpret_cast<float2*>(o0 + col) = v0;
            *reinterpret_cast<float2*>(o1 + col) = v1;
        }
    }
}

// ============================================================================
// Launch
// ============================================================================
extern "C" void kernel_launch(void* const* d_in, const int* in_sizes, int n_in,
                              void* d_out, int out_size) {
    const float* x = (const float*)d_in[0];
    const int* packed = (const int*)d_in[1];
    const float* absmax = (const float*)d_in[2];
    const float* bias = (const float*)d_in[3];
    float* out = (float*)d_out;

    dequant_kernel<<<dim3(K_TOTAL / 256, N_TOTAL / 16), 256>>>(packed, absmax);
    xprep_kernel<<<dim3(K_TOTAL / 256, M_TOTAL / 16), 256>>>(x);

    static bool attr_set = false;
    if (!attr_set) {
        cudaFuncSetAttribute(gemm_kernel,
                             cudaFuncAttributeMaxDynamicSharedMemorySize, SMEM_BYTES);
        attr_set = true;
    }
    gemm_kernel<<<GRID_M * GRID_N, 256, SMEM_BYTES>>>(out, bias);
}